// round 13
// baseline (speedup 1.0000x reference)
#include <cuda_runtime.h>
#include <cuda_bf16.h>
#include <mma.h>
#include <cstdint>

#define B_SZ 64
#define T_SZ 2048
#define K_SZ 256      // U_dim == X_dim
#define UN   256      // units

static __device__ __forceinline__ float softsign_exact(float z) {
    return z / (1.0f + fabsf(z));
}

#define BAR_SYNC(id, cnt)   asm volatile("bar.sync %0, %1;"   :: "r"(id), "r"(cnt) : "memory")
#define BAR_ARRIVE(id, cnt) asm volatile("bar.arrive %0, %1;" :: "r"(id), "r"(cnt) : "memory")

// ======= single fused kernel: GEMM + softsign scan + all GEMV epilogues =======
// 128 CTAs: b = blockIdx.x>>1, n0 = (blockIdx.x&1)*128. blockDim=320:
//   tid [0,256)   : GEMM warps (32x32 tiles, grid 2x4) that ALSO self-stage A
//                   (LDG fp32 -> hi/lo split -> STS), R6-style, bar 1 internal
//   tid [256,320) : scan warps (2 u-chains per thread) + I0 + output GEMVs
// Precision: chunks < PRECISE_C single-term bf16 (Xhi*Whi); softsign contraction
// annihilates their rounding error before Ys[-1]. Last 2 chunks use 3-term split.
// Barriers: staging bar 1 (256). OUT_READY[buf]=2+buf (320), OUT_FREE[buf]=4+buf
// (320) — one arrive-phase per sync-phase each (overrun-proof).
#define TM 64
#define TN 128
#define KC 32
#define A_LD 40      // 32 + 8 pad
#define B_LD 136     // 128 + 8 pad
#define O_LD 136

#define A_HALF  (TM * A_LD * 2)                   // 5120 B (one of hi/lo)
#define OFF_BHI 0
#define OFF_BLO (K_SZ * B_LD * 2)                 // 69632
#define OFF_A   (2 * (K_SZ * B_LD * 2))           // 139264
#define OFF_OUT (OFF_A + 4 * A_HALF)              // 159744
#define OUT_ELE (TM * O_LD)                       // floats per buffer
#define FUSED_SMEM (OFF_OUT + 2 * OUT_ELE * 4)    // 229376 bytes

#define NCHUNK (T_SZ / TM)        // 32
#define NKC    (K_SZ / KC)        // 8
#define NSTEP  (NCHUNK * NKC)     // 256
#define PRECISE_C (NCHUNK - 2)    // chunks >= this use full 3-term split

static __device__ __forceinline__ void split4(float4 v, uint2& hv, uint2& lv) {
    __nv_bfloat162 h01, h23, l01, l23;
    h01.x = __float2bfloat16(v.x); h01.y = __float2bfloat16(v.y);
    h23.x = __float2bfloat16(v.z); h23.y = __float2bfloat16(v.w);
    l01.x = __float2bfloat16(v.x - __bfloat162float(h01.x));
    l01.y = __float2bfloat16(v.y - __bfloat162float(h01.y));
    l23.x = __float2bfloat16(v.z - __bfloat162float(h23.x));
    l23.y = __float2bfloat16(v.w - __bfloat162float(h23.y));
    hv.x = *reinterpret_cast<uint32_t*>(&h01);
    hv.y = *reinterpret_cast<uint32_t*>(&h23);
    lv.x = *reinterpret_cast<uint32_t*>(&l01);
    lv.y = *reinterpret_cast<uint32_t*>(&l23);
}
static __device__ __forceinline__ uint2 pack_hi4(float4 v) {
    __nv_bfloat162 h01, h23;
    h01.x = __float2bfloat16(v.x); h01.y = __float2bfloat16(v.y);
    h23.x = __float2bfloat16(v.z); h23.y = __float2bfloat16(v.w);
    uint2 r;
    r.x = *reinterpret_cast<uint32_t*>(&h01);
    r.y = *reinterpret_cast<uint32_t*>(&h23);
    return r;
}

__global__ void __launch_bounds__(320, 1) fused_kernel(
        const float* __restrict__ U,
        const float* __restrict__ X,
        const float* __restrict__ W_i,
        const float* __restrict__ R_0,
        const float* __restrict__ b_0,
        const float* __restrict__ R_z,
        const float* __restrict__ b_z,
        const float* __restrict__ R_b,
        const float* __restrict__ W_p,
        const float* __restrict__ W_d,
        float* __restrict__ out) {
    using namespace nvcuda;
    extern __shared__ __align__(16) char smc[];
    __nv_bfloat16* const Bhi  = reinterpret_cast<__nv_bfloat16*>(smc + OFF_BHI);
    __nv_bfloat16* const Blo  = reinterpret_cast<__nv_bfloat16*>(smc + OFF_BLO);
    float*         const outs = reinterpret_cast<float*>(smc + OFF_OUT);

    const int tid = threadIdx.x;
    const int b   = blockIdx.x >> 1;
    const int n0  = (blockIdx.x & 1) * TN;
    const float* const Xb = X + (size_t)b * T_SZ * K_SZ;

    // ---- stage resident W half as hi/lo bf16 (GEMM warps; scan warps do I0) ----
    if (tid < 256) {
        for (int idx = tid; idx < K_SZ * (TN / 4); idx += 256) {   // 8192 float4
            int row = idx >> 5, c4 = idx & 31;
            float4 v = *reinterpret_cast<const float4*>(W_i + (size_t)row * UN + n0 + c4 * 4);
            uint2 hv, lv;
            split4(v, hv, lv);
            *reinterpret_cast<uint2*>(&Bhi[row * B_LD + c4 * 4]) = hv;
            *reinterpret_cast<uint2*>(&Blo[row * B_LD + c4 * 4]) = lv;
        }
    }

    if (tid < 256) {
        // ============ GEMM warps: self-staged A + 32x32 tiles (grid 2x4) ============
        const int wid = tid >> 5;
        const int wm  = wid >> 2;        // 0..1 : rows of 32
        const int wn  = wid & 3;         // 0..3 : cols of 32

        // A staging: 64 rows x 8 float4 per step = 512 float4 / 256 thr = 2 each
        const int xrow0 = tid >> 3,         xc40 = tid & 7;
        const int xrow1 = (tid + 256) >> 3, xc41 = (tid + 256) & 7;

        wmma::fragment<wmma::accumulator, 16, 16, 16, float> acc[2][2];
        #pragma unroll
        for (int i = 0; i < 2; i++)
            #pragma unroll
            for (int j = 0; j < 2; j++) wmma::fill_fragment(acc[i][j], 0.0f);

        float4 xr[2];
        xr[0] = *reinterpret_cast<const float4*>(Xb + (size_t)xrow0 * K_SZ + xc40 * 4);
        xr[1] = *reinterpret_cast<const float4*>(Xb + (size_t)xrow1 * K_SZ + xc41 * 4);

        __syncthreads();   // W resident + scan I0 done

        #pragma unroll 1
        for (int step = 0; step < NSTEP; step++) {
            const int c    = step >> 3;
            const int kc   = step & 7;
            const int abuf = step & 1;
            const bool precise = (c >= PRECISE_C);
            __nv_bfloat16* const Ah = reinterpret_cast<__nv_bfloat16*>(
                smc + OFF_A + abuf * 2 * A_HALF);
            __nv_bfloat16* const Al = reinterpret_cast<__nv_bfloat16*>(
                smc + OFF_A + abuf * 2 * A_HALF + A_HALF);

            // convert + STS this step's A (hi always; lo only when precise)
            if (precise) {
                uint2 hv, lv;
                split4(xr[0], hv, lv);
                *reinterpret_cast<uint2*>(&Ah[xrow0 * A_LD + xc40 * 4]) = hv;
                *reinterpret_cast<uint2*>(&Al[xrow0 * A_LD + xc40 * 4]) = lv;
                split4(xr[1], hv, lv);
                *reinterpret_cast<uint2*>(&Ah[xrow1 * A_LD + xc41 * 4]) = hv;
                *reinterpret_cast<uint2*>(&Al[xrow1 * A_LD + xc41 * 4]) = lv;
            } else {
                *reinterpret_cast<uint2*>(&Ah[xrow0 * A_LD + xc40 * 4]) = pack_hi4(xr[0]);
                *reinterpret_cast<uint2*>(&Ah[xrow1 * A_LD + xc41 * 4]) = pack_hi4(xr[1]);
            }
            // prefetch step+1
            if (step + 1 < NSTEP) {
                const int nc  = (step + 1) >> 3;
                const int nkc = (step + 1) & 7;
                const float* src = Xb + (size_t)(nc * TM) * K_SZ + nkc * KC;
                xr[0] = *reinterpret_cast<const float4*>(src + (size_t)xrow0 * K_SZ + xc40 * 4);
                xr[1] = *reinterpret_cast<const float4*>(src + (size_t)xrow1 * K_SZ + xc41 * 4);
            }
            BAR_SYNC(1, 256);   // staging visible; also fences A buffer reuse

            #pragma unroll
            for (int kk = 0; kk < KC; kk += 16) {
                const int krow = kc * KC + kk;
                wmma::fragment<wmma::matrix_a, 16, 16, 16, __nv_bfloat16, wmma::row_major> ah[2];
                wmma::fragment<wmma::matrix_b, 16, 16, 16, __nv_bfloat16, wmma::row_major> bh[2];
                #pragma unroll
                for (int i = 0; i < 2; i++)
                    wmma::load_matrix_sync(ah[i], &Ah[(wm * 32 + i * 16) * A_LD + kk], A_LD);
                #pragma unroll
                for (int j = 0; j < 2; j++)
                    wmma::load_matrix_sync(bh[j], &Bhi[krow * B_LD + wn * 32 + j * 16], B_LD);
                #pragma unroll
                for (int i = 0; i < 2; i++)
                    #pragma unroll
                    for (int j = 0; j < 2; j++)
                        wmma::mma_sync(acc[i][j], ah[i], bh[j], acc[i][j]);   // Xhi*Whi
                if (precise) {
                    wmma::fragment<wmma::matrix_a, 16, 16, 16, __nv_bfloat16, wmma::row_major> al[2];
                    wmma::fragment<wmma::matrix_b, 16, 16, 16, __nv_bfloat16, wmma::row_major> bl[2];
                    #pragma unroll
                    for (int i = 0; i < 2; i++)
                        wmma::load_matrix_sync(al[i], &Al[(wm * 32 + i * 16) * A_LD + kk], A_LD);
                    #pragma unroll
                    for (int j = 0; j < 2; j++)
                        wmma::load_matrix_sync(bl[j], &Blo[krow * B_LD + wn * 32 + j * 16], B_LD);
                    #pragma unroll
                    for (int i = 0; i < 2; i++)
                        #pragma unroll
                        for (int j = 0; j < 2; j++) {
                            wmma::mma_sync(acc[i][j], al[i], bh[j], acc[i][j]);   // Xlo*Whi
                            wmma::mma_sync(acc[i][j], ah[i], bl[j], acc[i][j]);   // Xhi*Wlo
                        }
                }
            }

            if (kc == 7) {
                const int ob_buf = c & 1;
                if (c >= 2) BAR_SYNC(4 + ob_buf, 320);      // OUT_FREE[buf]
                float* ob = outs + ob_buf * OUT_ELE;
                #pragma unroll
                for (int i = 0; i < 2; i++)
                    #pragma unroll
                    for (int j = 0; j < 2; j++) {
                        wmma::store_matrix_sync(&ob[(wm * 32 + i * 16) * O_LD + wn * 32 + j * 16],
                                                acc[i][j], O_LD, wmma::mem_row_major);
                        wmma::fill_fragment(acc[i][j], 0.0f);
                    }
                BAR_ARRIVE(2 + ob_buf, 320);                // OUT_READY[buf]
            }
        }
    } else {
        // ============ scan warps: I recurrence + I0 + all output GEMVs ============
        const int u0 = (tid - 256) * 2;   // 0,2,..,126 (local)
        const int ug = n0 + u0;           // global unit column (even)

        // I0 = U@R_0[:, ug(+1)] + b_0 (overlapped with W staging)
        float Ia = b_0[ug];
        float Ib = b_0[ug + 1];
        {
            const float* R0c = R_0 + ug;            // R_0 is [K_SZ][512]
            const float* Ubp = U + (size_t)b * K_SZ;
            #pragma unroll 8
            for (int k = 0; k < K_SZ; k++) {
                float uv = Ubp[k];
                Ia = fmaf(uv, R0c[(size_t)k * 512],     Ia);
                Ib = fmaf(uv, R0c[(size_t)k * 512 + 1], Ib);
            }
        }

        __syncthreads();   // pairs with GEMM warps' syncthreads

        float ub_a = 0.f, ub_b = 0.f;
        float zp_a = b_z[3 * ug],     zi_a = b_z[3 * ug + 1], zd_a = b_z[3 * ug + 2];
        float zp_b = b_z[3 * ug + 3], zi_b = b_z[3 * ug + 4], zd_b = b_z[3 * ug + 5];
        float p_a = 0.f, p_b = 0.f, d_a = 0.f, d_b = 0.f;
        const float* const Ubp = U + (size_t)b * K_SZ;
        const float* const xlp = Xb + (size_t)(T_SZ - 1) * K_SZ;
        const float* const xpp = Xb + (size_t)(T_SZ - 2) * K_SZ;

        #pragma unroll 1
        for (int c = 0; c < NCHUNK; c++) {
            const int ob_buf = c & 1;
            BAR_SYNC(2 + ob_buf, 320);                      // OUT_READY[buf]
            const float* ob = outs + ob_buf * OUT_ELE;
            const float2* obp = reinterpret_cast<const float2*>(ob) + (u0 >> 1);
            float2 v  = obp[0];
            float2 vn = obp[O_LD / 2];
            #pragma unroll 8
            for (int t = 0; t < TM; t++) {
                float za = Ia + v.x;
                float zb = Ib + v.y;
                v = vn;
                if (t + 2 < TM) vn = obp[(size_t)(t + 2) * (O_LD / 2)];
                Ia = __fdividef(za, 1.0f + fabsf(za));
                Ib = __fdividef(zb, 1.0f + fabsf(zb));
            }
            BAR_ARRIVE(4 + ob_buf, 320);                    // OUT_FREE[buf]

            // ---- epilogue k-slice [8c, 8c+8) (hidden in scan slack) ----
            #pragma unroll
            for (int kk = 0; kk < 8; kk++) {
                const int k = c * 8 + kk;
                float uv  = Ubp[k];
                float xlv = xlp[k];
                float dxv = xlv - xpp[k];
                float2 rb  = *reinterpret_cast<const float2*>(R_b + (size_t)k * UN + ug);
                float2 rz0 = *reinterpret_cast<const float2*>(R_z + (size_t)k * 768 + 3 * ug);
                float2 rz1 = *reinterpret_cast<const float2*>(R_z + (size_t)k * 768 + 3 * ug + 2);
                float2 rz2 = *reinterpret_cast<const float2*>(R_z + (size_t)k * 768 + 3 * ug + 4);
                float2 wp  = *reinterpret_cast<const float2*>(W_p + (size_t)k * UN + ug);
                float2 wd  = *reinterpret_cast<const float2*>(W_d + (size_t)k * UN + ug);
                ub_a = fmaf(uv, rb.x, ub_a);   ub_b = fmaf(uv, rb.y, ub_b);
                zp_a = fmaf(uv, rz0.x, zp_a);  zi_a = fmaf(uv, rz0.y, zi_a);
                zd_a = fmaf(uv, rz1.x, zd_a);  zp_b = fmaf(uv, rz1.y, zp_b);
                zi_b = fmaf(uv, rz2.x, zi_b);  zd_b = fmaf(uv, rz2.y, zd_b);
                p_a  = fmaf(xlv, wp.x, p_a);   p_b  = fmaf(xlv, wp.y, p_b);
                d_a  = fmaf(dxv, wd.x, d_a);   d_b  = fmaf(dxv, wd.y, d_b);
            }
        }

        float Pa = softsign_exact(ub_a + p_a);
        float Pb = softsign_exact(ub_b + p_b);
        float Da = softsign_exact(d_a);
        float Db = softsign_exact(d_b);
        float2 r;
        r.x = zp_a * Pa + zi_a * Ia + zd_a * Da;
        r.y = zp_b * Pb + zi_b * Ib + zd_b * Db;
        *reinterpret_cast<float2*>(out + (size_t)b * UN + ug) = r;
    }
}

// ---------------- launcher ----------------
extern "C" void kernel_launch(void* const* d_in, const int* in_sizes, int n_in,
                              void* d_out, int out_size) {
    const float* U   = (const float*)d_in[0];
    const float* X   = (const float*)d_in[1];
    const float* R_z = (const float*)d_in[2];
    const float* b_z = (const float*)d_in[3];
    const float* R_0 = (const float*)d_in[4];
    const float* b_0 = (const float*)d_in[5];
    const float* R_b = (const float*)d_in[6];
    const float* W_p = (const float*)d_in[7];
    const float* W_i = (const float*)d_in[8];
    const float* W_d = (const float*)d_in[9];
    float* out = (float*)d_out;

    cudaFuncSetAttribute(fused_kernel,
                         cudaFuncAttributeMaxDynamicSharedMemorySize, FUSED_SMEM);

    fused_kernel<<<2 * B_SZ, 320, FUSED_SMEM>>>(U, X, W_i, R_0, b_0,
                                                R_z, b_z, R_b, W_p, W_d, out);
}

// round 14
// speedup vs baseline: 1.3782x; 1.3782x over previous
#include <cuda_runtime.h>
#include <cuda_bf16.h>
#include <mma.h>
#include <cstdint>

#define B_SZ 64
#define T_SZ 2048
#define K_SZ 256      // U_dim == X_dim
#define UN   256      // units

static __device__ __forceinline__ float softsign_exact(float z) {
    return z / (1.0f + fabsf(z));
}

#define BAR_SYNC(id, cnt)   asm volatile("bar.sync %0, %1;"   :: "r"(id), "r"(cnt) : "memory")
#define BAR_ARRIVE(id, cnt) asm volatile("bar.arrive %0, %1;" :: "r"(id), "r"(cnt) : "memory")

// ======= single fused kernel: GEMM + softsign scan + all GEMV epilogues =======
// 128 CTAs: b = blockIdx.x>>1, n0 = (blockIdx.x&1)*128. blockDim=384:
//   tid [0,256)   : GEMM warps (32x32 tiles, grid 2x4), KC=64 per handshake
//   tid [256,320) : staging warps (A fp32->hi/lo->STS; Wlo chunk in precise steps)
//   tid [320,384) : scan warps (2 u-chains per thread) + I0 + output GEMVs
// Precision: chunks < PRECISE_C single-term bf16 (Xhi*Whi); softsign contraction
// annihilates old rounding error. Last 2 chunks (128 t-steps) use 3-term split;
// Wlo for those is staged on the fly (W_i is L2-resident), not smem-resident.
// Barriers: A_READY[buf]=6+buf (320), A_FREE[buf]=8+buf (320),
//           OUT_READY[buf]=2+buf (320), OUT_FREE[buf]=4+buf (320).
// Each has exactly one arrive-phase per sync-phase (overrun-proof).
#define TM 64
#define KC 64
#define A_LD 72      // 64 + 8 pad (144 B rows)
#define B_LD 136     // 128 + 8 pad
#define O_LD 136

#define A_HALF  (TM * A_LD * 2)                   // 9216 B (one of hi/lo)
#define BLO_BUF (KC * B_LD * 2)                   // 17408 B
#define OFF_BHI 0                                 // 256*136*2 = 69632
#define OFF_BLO 69632                             // 2 bufs -> 34816
#define OFF_A   104448                            // 2 bufs x 2 halves -> 36864
#define OFF_OUT 141312                            // 2 x 64*136*4 = 69632
#define OUT_ELE (TM * O_LD)
#define FUSED_SMEM 210944

#define NCHUNK (T_SZ / TM)        // 32
#define NKC    (K_SZ / KC)        // 4
#define NSTEP  (NCHUNK * NKC)     // 128
#define PRECISE_C (NCHUNK - 2)    // chunks >= this use full 3-term split

static __device__ __forceinline__ void split4(float4 v, uint2& hv, uint2& lv) {
    __nv_bfloat162 h01, h23, l01, l23;
    h01.x = __float2bfloat16(v.x); h01.y = __float2bfloat16(v.y);
    h23.x = __float2bfloat16(v.z); h23.y = __float2bfloat16(v.w);
    l01.x = __float2bfloat16(v.x - __bfloat162float(h01.x));
    l01.y = __float2bfloat16(v.y - __bfloat162float(h01.y));
    l23.x = __float2bfloat16(v.z - __bfloat162float(h23.x));
    l23.y = __float2bfloat16(v.w - __bfloat162float(h23.y));
    hv.x = *reinterpret_cast<uint32_t*>(&h01);
    hv.y = *reinterpret_cast<uint32_t*>(&h23);
    lv.x = *reinterpret_cast<uint32_t*>(&l01);
    lv.y = *reinterpret_cast<uint32_t*>(&l23);
}
static __device__ __forceinline__ uint2 pack_hi4(float4 v) {
    __nv_bfloat162 h01, h23;
    h01.x = __float2bfloat16(v.x); h01.y = __float2bfloat16(v.y);
    h23.x = __float2bfloat16(v.z); h23.y = __float2bfloat16(v.w);
    uint2 r;
    r.x = *reinterpret_cast<uint32_t*>(&h01);
    r.y = *reinterpret_cast<uint32_t*>(&h23);
    return r;
}
static __device__ __forceinline__ uint2 pack_lo4(float4 v) {
    __nv_bfloat162 l01, l23;
    l01.x = __float2bfloat16(v.x - __bfloat162float(__float2bfloat16(v.x)));
    l01.y = __float2bfloat16(v.y - __bfloat162float(__float2bfloat16(v.y)));
    l23.x = __float2bfloat16(v.z - __bfloat162float(__float2bfloat16(v.z)));
    l23.y = __float2bfloat16(v.w - __bfloat162float(__float2bfloat16(v.w)));
    uint2 r;
    r.x = *reinterpret_cast<uint32_t*>(&l01);
    r.y = *reinterpret_cast<uint32_t*>(&l23);
    return r;
}

__global__ void __launch_bounds__(384, 1) fused_kernel(
        const float* __restrict__ U,
        const float* __restrict__ X,
        const float* __restrict__ W_i,
        const float* __restrict__ R_0,
        const float* __restrict__ b_0,
        const float* __restrict__ R_z,
        const float* __restrict__ b_z,
        const float* __restrict__ R_b,
        const float* __restrict__ W_p,
        const float* __restrict__ W_d,
        float* __restrict__ out) {
    using namespace nvcuda;
    extern __shared__ __align__(16) char smc[];
    __nv_bfloat16* const Bhi  = reinterpret_cast<__nv_bfloat16*>(smc + OFF_BHI);
    float*         const outs = reinterpret_cast<float*>(smc + OFF_OUT);

    const int tid = threadIdx.x;
    const int b   = blockIdx.x >> 1;
    const int n0  = (blockIdx.x & 1) * 128;
    const float* const Xb = X + (size_t)b * T_SZ * K_SZ;

    // ---- stage resident W_hi half (warps 0-9; scan warps do I0) ----
    if (tid < 320) {
        for (int idx = tid; idx < K_SZ * 32; idx += 320) {   // 8192 float4
            int row = idx >> 5, c4 = idx & 31;
            float4 v = *reinterpret_cast<const float4*>(W_i + (size_t)row * UN + n0 + c4 * 4);
            *reinterpret_cast<uint2*>(&Bhi[row * B_LD + c4 * 4]) = pack_hi4(v);
        }
    }
    __syncthreads();

    if (tid < 256) {
        // ======================= GEMM warps (pure compute) =======================
        const int wid = tid >> 5;
        const int wm  = wid >> 2;        // 0..1 : rows of 32
        const int wn  = wid & 3;         // 0..3 : cols of 32

        wmma::fragment<wmma::accumulator, 16, 16, 16, float> acc[2][2];
        #pragma unroll
        for (int i = 0; i < 2; i++)
            #pragma unroll
            for (int j = 0; j < 2; j++) wmma::fill_fragment(acc[i][j], 0.0f);

        #pragma unroll 1
        for (int step = 0; step < NSTEP; step++) {
            const int c    = step >> 2;
            const int kc   = step & 3;
            const int abuf = step & 1;
            const bool precise = (c >= PRECISE_C);
            __nv_bfloat16* const Ah = reinterpret_cast<__nv_bfloat16*>(
                smc + OFF_A + abuf * 2 * A_HALF);
            __nv_bfloat16* const Al = reinterpret_cast<__nv_bfloat16*>(
                smc + OFF_A + abuf * 2 * A_HALF + A_HALF);
            __nv_bfloat16* const Bl = reinterpret_cast<__nv_bfloat16*>(
                smc + OFF_BLO + abuf * BLO_BUF);

            BAR_SYNC(6 + abuf, 320);     // A_READY[abuf]

            #pragma unroll
            for (int kk = 0; kk < KC; kk += 16) {
                const int krow = kc * KC + kk;
                wmma::fragment<wmma::matrix_a, 16, 16, 16, __nv_bfloat16, wmma::row_major> ah[2];
                wmma::fragment<wmma::matrix_b, 16, 16, 16, __nv_bfloat16, wmma::row_major> bh[2];
                #pragma unroll
                for (int i = 0; i < 2; i++)
                    wmma::load_matrix_sync(ah[i], &Ah[(wm * 32 + i * 16) * A_LD + kk], A_LD);
                #pragma unroll
                for (int j = 0; j < 2; j++)
                    wmma::load_matrix_sync(bh[j], &Bhi[krow * B_LD + wn * 32 + j * 16], B_LD);
                #pragma unroll
                for (int i = 0; i < 2; i++)
                    #pragma unroll
                    for (int j = 0; j < 2; j++)
                        wmma::mma_sync(acc[i][j], ah[i], bh[j], acc[i][j]);   // Xhi*Whi
                if (precise) {
                    wmma::fragment<wmma::matrix_a, 16, 16, 16, __nv_bfloat16, wmma::row_major> al[2];
                    wmma::fragment<wmma::matrix_b, 16, 16, 16, __nv_bfloat16, wmma::row_major> bl[2];
                    #pragma unroll
                    for (int i = 0; i < 2; i++)
                        wmma::load_matrix_sync(al[i], &Al[(wm * 32 + i * 16) * A_LD + kk], A_LD);
                    #pragma unroll
                    for (int j = 0; j < 2; j++)
                        wmma::load_matrix_sync(bl[j], &Bl[kk * B_LD + wn * 32 + j * 16], B_LD);
                    #pragma unroll
                    for (int i = 0; i < 2; i++)
                        #pragma unroll
                        for (int j = 0; j < 2; j++) {
                            wmma::mma_sync(acc[i][j], al[i], bh[j], acc[i][j]);   // Xlo*Whi
                            wmma::mma_sync(acc[i][j], ah[i], bl[j], acc[i][j]);   // Xhi*Wlo
                        }
                }
            }
            BAR_ARRIVE(8 + abuf, 320);   // A_FREE[abuf]

            if (kc == 3) {
                const int ob_buf = c & 1;
                if (c >= 2) BAR_SYNC(4 + ob_buf, 320);      // OUT_FREE[buf]
                float* ob = outs + ob_buf * OUT_ELE;
                #pragma unroll
                for (int i = 0; i < 2; i++)
                    #pragma unroll
                    for (int j = 0; j < 2; j++) {
                        wmma::store_matrix_sync(&ob[(wm * 32 + i * 16) * O_LD + wn * 32 + j * 16],
                                                acc[i][j], O_LD, wmma::mem_row_major);
                        wmma::fill_fragment(acc[i][j], 0.0f);
                    }
                BAR_ARRIVE(2 + ob_buf, 320);                // OUT_READY[buf]
            }
        }
    } else if (tid < 320) {
        // ======================= staging warps (A, and Wlo when precise) ==========
        const int st = tid - 256;        // 0..63
        // A: 64 rows x 16 float4 per step (KC=64 cols) = 1024 float4 / 64 = 16 each
        int rowv[16], c4v[16];
        #pragma unroll
        for (int r = 0; r < 16; r++) {
            int i = r * 64 + st;
            rowv[r] = i >> 4;
            c4v[r]  = i & 15;
        }
        float4 xr[16];
        #pragma unroll
        for (int r = 0; r < 16; r++)
            xr[r] = *reinterpret_cast<const float4*>(
                Xb + (size_t)rowv[r] * K_SZ + c4v[r] * 4);

        #pragma unroll 1
        for (int step = 0; step < NSTEP; step++) {
            const int abuf = step & 1;
            const int c    = step >> 2;
            const int kc   = step & 3;
            const bool precise = (c >= PRECISE_C);
            __nv_bfloat16* const Ah = reinterpret_cast<__nv_bfloat16*>(
                smc + OFF_A + abuf * 2 * A_HALF);
            __nv_bfloat16* const Al = reinterpret_cast<__nv_bfloat16*>(
                smc + OFF_A + abuf * 2 * A_HALF + A_HALF);
            __nv_bfloat16* const Bl = reinterpret_cast<__nv_bfloat16*>(
                smc + OFF_BLO + abuf * BLO_BUF);

            if (step >= 2) BAR_SYNC(8 + abuf, 320);   // A_FREE[abuf]
            if (precise) {
                #pragma unroll
                for (int r = 0; r < 16; r++) {
                    uint2 hv, lv;
                    split4(xr[r], hv, lv);
                    *reinterpret_cast<uint2*>(&Ah[rowv[r] * A_LD + c4v[r] * 4]) = hv;
                    *reinterpret_cast<uint2*>(&Al[rowv[r] * A_LD + c4v[r] * 4]) = lv;
                }
                // stage Wlo chunk: rows kc*64..+64 of [K][n0..n0+128) (L2-hit)
                #pragma unroll
                for (int it = 0; it < 32; it++) {
                    int i = it * 64 + st;            // 0..2047
                    int row = i >> 5, cc = i & 31;   // 32 float4 per 128-col row
                    float4 w = *reinterpret_cast<const float4*>(
                        W_i + (size_t)(kc * KC + row) * UN + n0 + cc * 4);
                    *reinterpret_cast<uint2*>(&Bl[row * B_LD + cc * 4]) = pack_lo4(w);
                }
            } else {
                #pragma unroll
                for (int r = 0; r < 16; r++)
                    *reinterpret_cast<uint2*>(&Ah[rowv[r] * A_LD + c4v[r] * 4]) = pack_hi4(xr[r]);
            }
            BAR_ARRIVE(6 + abuf, 320);                // A_READY[abuf]

            if (step + 1 < NSTEP) {
                const int nc  = (step + 1) >> 2;
                const int nkc = (step + 1) & 3;
                const float* src = Xb + (size_t)(nc * TM) * K_SZ + nkc * KC;
                #pragma unroll
                for (int r = 0; r < 16; r++)
                    xr[r] = *reinterpret_cast<const float4*>(
                        src + (size_t)rowv[r] * K_SZ + c4v[r] * 4);
            }
        }
    } else {
        // ============ scan warps: I recurrence + I0 + all output GEMVs ============
        const int u0 = (tid - 320) * 2;   // 0,2,..,126 (local)
        const int ug = n0 + u0;           // global unit column (even)

        float Ia = b_0[ug];
        float Ib = b_0[ug + 1];
        {
            const float* R0c = R_0 + ug;            // R_0 is [K_SZ][512]
            const float* Ubp = U + (size_t)b * K_SZ;
            #pragma unroll 8
            for (int k = 0; k < K_SZ; k++) {
                float uv = Ubp[k];
                Ia = fmaf(uv, R0c[(size_t)k * 512],     Ia);
                Ib = fmaf(uv, R0c[(size_t)k * 512 + 1], Ib);
            }
        }

        float ub_a = 0.f, ub_b = 0.f;
        float zp_a = b_z[3 * ug],     zi_a = b_z[3 * ug + 1], zd_a = b_z[3 * ug + 2];
        float zp_b = b_z[3 * ug + 3], zi_b = b_z[3 * ug + 4], zd_b = b_z[3 * ug + 5];
        float p_a = 0.f, p_b = 0.f, d_a = 0.f, d_b = 0.f;
        const float* const Ubp = U + (size_t)b * K_SZ;
        const float* const xlp = Xb + (size_t)(T_SZ - 1) * K_SZ;
        const float* const xpp = Xb + (size_t)(T_SZ - 2) * K_SZ;

        #pragma unroll 1
        for (int c = 0; c < NCHUNK; c++) {
            const int ob_buf = c & 1;
            BAR_SYNC(2 + ob_buf, 320);                      // OUT_READY[buf]
            const float* ob = outs + ob_buf * OUT_ELE;
            const float2* obp = reinterpret_cast<const float2*>(ob) + (u0 >> 1);
            float2 v  = obp[0];
            float2 vn = obp[O_LD / 2];
            #pragma unroll 8
            for (int t = 0; t < TM; t++) {
                float za = Ia + v.x;
                float zb = Ib + v.y;
                v = vn;
                if (t + 2 < TM) vn = obp[(size_t)(t + 2) * (O_LD / 2)];
                Ia = __fdividef(za, 1.0f + fabsf(za));
                Ib = __fdividef(zb, 1.0f + fabsf(zb));
            }
            BAR_ARRIVE(4 + ob_buf, 320);                    // OUT_FREE[buf]

            // ---- epilogue k-slice [8c, 8c+8) (hidden in scan slack) ----
            #pragma unroll
            for (int kk = 0; kk < 8; kk++) {
                const int k = c * 8 + kk;
                float uv  = Ubp[k];
                float xlv = xlp[k];
                float dxv = xlv - xpp[k];
                float2 rb  = *reinterpret_cast<const float2*>(R_b + (size_t)k * UN + ug);
                float2 rz0 = *reinterpret_cast<const float2*>(R_z + (size_t)k * 768 + 3 * ug);
                float2 rz1 = *reinterpret_cast<const float2*>(R_z + (size_t)k * 768 + 3 * ug + 2);
                float2 rz2 = *reinterpret_cast<const float2*>(R_z + (size_t)k * 768 + 3 * ug + 4);
                float2 wp  = *reinterpret_cast<const float2*>(W_p + (size_t)k * UN + ug);
                float2 wd  = *reinterpret_cast<const float2*>(W_d + (size_t)k * UN + ug);
                ub_a = fmaf(uv, rb.x, ub_a);   ub_b = fmaf(uv, rb.y, ub_b);
                zp_a = fmaf(uv, rz0.x, zp_a);  zi_a = fmaf(uv, rz0.y, zi_a);
                zd_a = fmaf(uv, rz1.x, zd_a);  zp_b = fmaf(uv, rz1.y, zp_b);
                zi_b = fmaf(uv, rz2.x, zi_b);  zd_b = fmaf(uv, rz2.y, zd_b);
                p_a  = fmaf(xlv, wp.x, p_a);   p_b  = fmaf(xlv, wp.y, p_b);
                d_a  = fmaf(dxv, wd.x, d_a);   d_b  = fmaf(dxv, wd.y, d_b);
            }
        }

        float Pa = softsign_exact(ub_a + p_a);
        float Pb = softsign_exact(ub_b + p_b);
        float Da = softsign_exact(d_a);
        float Db = softsign_exact(d_b);
        float2 r;
        r.x = zp_a * Pa + zi_a * Ia + zd_a * Da;
        r.y = zp_b * Pb + zi_b * Ib + zd_b * Db;
        *reinterpret_cast<float2*>(out + (size_t)b * UN + ug) = r;
    }
}

// ---------------- launcher ----------------
extern "C" void kernel_launch(void* const* d_in, const int* in_sizes, int n_in,
                              void* d_out, int out_size) {
    const float* U   = (const float*)d_in[0];
    const float* X   = (const float*)d_in[1];
    const float* R_z = (const float*)d_in[2];
    const float* b_z = (const float*)d_in[3];
    const float* R_0 = (const float*)d_in[4];
    const float* b_0 = (const float*)d_in[5];
    const float* R_b = (const float*)d_in[6];
    const float* W_p = (const float*)d_in[7];
    const float* W_i = (const float*)d_in[8];
    const float* W_d = (const float*)d_in[9];
    float* out = (float*)d_out;

    cudaFuncSetAttribute(fused_kernel,
                         cudaFuncAttributeMaxDynamicSharedMemorySize, FUSED_SMEM);

    fused_kernel<<<2 * B_SZ, 384, FUSED_SMEM>>>(U, X, W_i, R_0, b_0,
                                                R_z, b_z, R_b, W_p, W_d, out);
}